// round 3
// baseline (speedup 1.0000x reference)
#include <cuda_runtime.h>
#include <math.h>

#define B  8
#define C  64
#define Hc 256
#define Wc 256
#define CR 128
#define HR 128
#define WR 128

__device__ float g_part[B * CR * 2];   // half-plane partial sums
__device__ int   g_idx[B * C];

// ---------------------------------------------------------------------------
// Kernel 1: half-plane partial of the analytic upsample-mean score.
// grid = B*CR*2 blocks; each block handles 2048 float4 (8 per thread).
// ---------------------------------------------------------------------------
__global__ void __launch_bounds__(256) scores_kernel(const float* __restrict__ readout) {
    __shared__ float wA[HR];
    __shared__ float red[8];
    const int tid = threadIdx.x;

    if (tid < HR) wA[tid] = 0.0f;
    __syncthreads();
    {
        const float cst = (float)(127.0 / 255.0);
        float pos = (float)tid * cst;
        int i0 = (int)pos;
        if (i0 > HR - 2) i0 = HR - 2;
        float w = pos - (float)i0;
        atomicAdd(&wA[i0], 1.0f - w);
        atomicAdd(&wA[i0 + 1], w);
    }
    __syncthreads();

    const int blk   = blockIdx.x;          // plane*2 + half
    const int plane = blk >> 1;
    const int half  = blk & 1;
    const float4* __restrict__ src =
        (const float4*)(readout + (size_t)plane * (HR * WR)) + half * 2048;

    float4 v[8];
    #pragma unroll
    for (int j = 0; j < 8; j++)
        v[j] = src[tid + j * 256];

    float acc0 = 0.f, acc1 = 0.f, acc2 = 0.f, acc3 = 0.f;
    #pragma unroll
    for (int j = 0; j < 8; j++) {
        int idx4 = half * 2048 + tid + j * 256;
        int row = idx4 >> 5;               // (idx4*4)/128
        int col = (idx4 << 2) & 127;
        float wr = wA[row];
        float s = wA[col] * v[j].x + wA[col + 1] * v[j].y +
                  wA[col + 2] * v[j].z + wA[col + 3] * v[j].w;
        if (j == 0 || j == 4) acc0 += wr * s;
        else if (j == 1 || j == 5) acc1 += wr * s;
        else if (j == 2 || j == 6) acc2 += wr * s;
        else acc3 += wr * s;
    }

    float acc = (acc0 + acc1) + (acc2 + acc3);
    #pragma unroll
    for (int s = 16; s > 0; s >>= 1)
        acc += __shfl_down_sync(0xffffffffu, acc, s);
    if ((tid & 31) == 0) red[tid >> 5] = acc;
    __syncthreads();
    if (tid == 0) {
        float t = 0.f;
        #pragma unroll
        for (int w2 = 0; w2 < 8; w2++) t += red[w2];
        g_part[blk] = t;
    }
}

// ---------------------------------------------------------------------------
// Kernel 2: combine partials + per-batch descending bitonic sort (tie: lower
// index first, matching jax.lax.top_k). Writes top C=64 indices.
// ---------------------------------------------------------------------------
__global__ void topk_kernel() {
    __shared__ float sv[CR];
    __shared__ int   si[CR];
    const int tid = threadIdx.x;  // 0..127
    const int b = blockIdx.x;

    const int p = b * CR + tid;
    sv[tid] = (g_part[2 * p] + g_part[2 * p + 1]) * (1.0f / (float)(Hc * Wc));
    si[tid] = tid;
    __syncthreads();

    for (int k = 2; k <= CR; k <<= 1) {
        for (int j = k >> 1; j > 0; j >>= 1) {
            int ixj = tid ^ j;
            if (ixj > tid) {
                float va = sv[tid], vb = sv[ixj];
                int   ia = si[tid], ib = si[ixj];
                bool first = (va > vb) || (va == vb && ia < ib);
                bool ascSeg = ((tid & k) == 0);
                bool doSwap = ascSeg ? (!first) : first;
                if (doSwap) {
                    sv[tid] = vb; sv[ixj] = va;
                    si[tid] = ib; si[ixj] = ia;
                }
            }
            __syncthreads();
        }
    }

    if (tid < C) g_idx[b * C + tid] = si[tid];
}

// ---------------------------------------------------------------------------
// Kernel 3: fused bilinear-upsample + gated blend.
// Block = 16 output rows x 256 cols of one plane (512 threads).
// Per thread: 8 contiguous pixels; 2 front-batched streamed float4 x-loads
// issued BEFORE the staging barrier, 2 streamed float4 stores.
// ---------------------------------------------------------------------------
__global__ void __launch_bounds__(512) fuse_kernel(
    const float* __restrict__ x,
    const float* __restrict__ readout,
    const float* __restrict__ weight,
    const float* __restrict__ bias,
    float* __restrict__ out)
{
    __shared__ float srow[10 * WR];

    const int plane = blockIdx.z;            // b*C + c
    const int b = plane >> 6;
    const int c = plane & (C - 1);
    const int ch = g_idx[plane];

    const float* __restrict__ rsrc =
        readout + ((size_t)b * CR + ch) * (HR * WR);

    const int y0 = blockIdx.y << 4;          // 16 rows per block
    const float cst = (float)(127.0 / 255.0);

    int iy_lo = (int)((float)y0 * cst);        if (iy_lo > HR - 2) iy_lo = HR - 2;
    int iy_hi = (int)((float)(y0 + 15) * cst); if (iy_hi > HR - 2) iy_hi = HR - 2;
    iy_hi += 1;
    const int nrows = iy_hi - iy_lo + 1;      // <= 10

    const int tid = threadIdx.x;
    const bool do_stage = (tid < nrows * 32);
    float4 sv4;
    if (do_stage)
        sv4 = *(const float4*)(rsrc + (iy_lo + (tid >> 5)) * WR + ((tid & 31) << 2));

    const int ty = tid >> 5;                  // 0..15 (row within tile)
    const int tx = tid & 31;
    const int x0 = tx << 3;                   // 8 px per thread
    const int y  = y0 + ty;

    const size_t o = ((size_t)plane * Hc + y) * Wc + x0;
    float4 xv0 = __ldcs((const float4*)(x + o));
    float4 xv1 = __ldcs((const float4*)(x + o + 4));

    if (do_stage)
        *(float4*)(srow + (tid >> 5) * WR + ((tid & 31) << 2)) = sv4;
    __syncthreads();

    float posy = (float)y * cst;
    int iy0 = (int)posy;
    if (iy0 > HR - 2) iy0 = HR - 2;
    const float wy = posy - (float)iy0;
    const float wy0 = 1.0f - wy;

    const float* __restrict__ s0 = srow + (iy0 - iy_lo) * WR;
    const float* __restrict__ s1 = s0 + WR;

    const float w0 = __ldg(weight + 2 * c);
    const float w1 = __ldg(weight + 2 * c + 1);
    const float bs = __ldg(bias + c);

    float xs[8] = {xv0.x, xv0.y, xv0.z, xv0.w, xv1.x, xv1.y, xv1.z, xv1.w};
    float os[8];

    #pragma unroll
    for (int k = 0; k < 8; k++) {
        float posx = (float)(x0 + k) * cst;
        int ix0 = (int)posx;
        if (ix0 > WR - 2) ix0 = WR - 2;
        float wx = posx - (float)ix0;
        // match reference: interpolate along H first, then W
        float a  = s0[ix0]     * wy0 + s1[ix0]     * wy;
        float bb = s0[ix0 + 1] * wy0 + s1[ix0 + 1] * wy;
        float rv = a * (1.0f - wx) + bb * wx;
        float t = xs[k] * w0 + rv * w1 + bs;
        float gate = 1.0f / (1.0f + __expf(-t));
        os[k] = xs[k] + gate * (rv - xs[k]);
    }

    __stcs((float4*)(out + o),     make_float4(os[0], os[1], os[2], os[3]));
    __stcs((float4*)(out + o + 4), make_float4(os[4], os[5], os[6], os[7]));
}

// ---------------------------------------------------------------------------
extern "C" void kernel_launch(void* const* d_in, const int* in_sizes, int n_in,
                              void* d_out, int out_size)
{
    const float* x       = (const float*)d_in[0];
    const float* readout = (const float*)d_in[1];
    const float* weight  = (const float*)d_in[2];
    const float* bias    = (const float*)d_in[3];
    float* out = (float*)d_out;

    scores_kernel<<<B * CR * 2, 256>>>(readout);
    topk_kernel<<<B, CR>>>();

    dim3 blk(512, 1, 1);
    dim3 grd(1, Hc / 16, B * C);   // (1, 16, 512)
    fuse_kernel<<<grd, blk>>>(x, readout, weight, bias, out);
}

// round 4
// speedup vs baseline: 1.3426x; 1.3426x over previous
#include <cuda_runtime.h>
#include <math.h>

#define B  8
#define C  64
#define Hc 256
#define Wc 256
#define CR 128
#define HR 128
#define WR 128

__device__ float g_scores[B * CR];
__device__ int   g_idx[B * C];

// ---------------------------------------------------------------------------
// Kernel 1: per-(b,cr) score = mean of bilinear-2x-upsampled plane (analytic
// separable weighted sum). Proven R2 version: 16 float4 loads in 2 batches.
// ---------------------------------------------------------------------------
__global__ void __launch_bounds__(256) scores_kernel(const float* __restrict__ readout) {
    __shared__ float wA[HR];
    __shared__ float red[8];
    const int tid = threadIdx.x;

    if (tid < HR) wA[tid] = 0.0f;
    __syncthreads();
    {
        const float cst = (float)(127.0 / 255.0);
        float pos = (float)tid * cst;
        int i0 = (int)pos;
        if (i0 > HR - 2) i0 = HR - 2;
        float w = pos - (float)i0;
        atomicAdd(&wA[i0], 1.0f - w);
        atomicAdd(&wA[i0 + 1], w);
    }
    __syncthreads();

    const int plane = blockIdx.x;
    const float4* __restrict__ src =
        (const float4*)(readout + (size_t)plane * (HR * WR));

    float acc0 = 0.f, acc1 = 0.f, acc2 = 0.f, acc3 = 0.f;

    #pragma unroll
    for (int half = 0; half < 2; half++) {
        float4 v[8];
        #pragma unroll
        for (int j = 0; j < 8; j++)
            v[j] = src[tid + (half * 8 + j) * 256];

        #pragma unroll
        for (int j = 0; j < 8; j++) {
            int base = (tid + (half * 8 + j) * 256) << 2;
            int row = base >> 7;
            int col = base & 127;
            float wr = wA[row];
            float s = wA[col] * v[j].x + wA[col + 1] * v[j].y +
                      wA[col + 2] * v[j].z + wA[col + 3] * v[j].w;
            if (j == 0 || j == 4) acc0 += wr * s;
            else if (j == 1 || j == 5) acc1 += wr * s;
            else if (j == 2 || j == 6) acc2 += wr * s;
            else acc3 += wr * s;
        }
    }

    float acc = (acc0 + acc1) + (acc2 + acc3);
    #pragma unroll
    for (int s = 16; s > 0; s >>= 1)
        acc += __shfl_down_sync(0xffffffffu, acc, s);
    if ((tid & 31) == 0) red[tid >> 5] = acc;
    __syncthreads();
    if (tid == 0) {
        float t = 0.f;
        #pragma unroll
        for (int w2 = 0; w2 < 8; w2++) t += red[w2];
        g_scores[plane] = t * (1.0f / (float)(Hc * Wc));
    }
}

// ---------------------------------------------------------------------------
// Kernel 2: per-batch descending bitonic sort of 128 scores (tie: lower idx
// first, matching jax.lax.top_k). Writes the top C=64 indices.
// ---------------------------------------------------------------------------
__global__ void topk_kernel() {
    __shared__ float sv[CR];
    __shared__ int   si[CR];
    const int tid = threadIdx.x;
    const int b = blockIdx.x;

    sv[tid] = g_scores[b * CR + tid];
    si[tid] = tid;
    __syncthreads();

    for (int k = 2; k <= CR; k <<= 1) {
        for (int j = k >> 1; j > 0; j >>= 1) {
            int ixj = tid ^ j;
            if (ixj > tid) {
                float va = sv[tid], vb = sv[ixj];
                int   ia = si[tid], ib = si[ixj];
                bool first = (va > vb) || (va == vb && ia < ib);
                bool ascSeg = ((tid & k) == 0);
                bool doSwap = ascSeg ? (!first) : first;
                if (doSwap) {
                    sv[tid] = vb; sv[ixj] = va;
                    si[tid] = ib; si[ixj] = ia;
                }
            }
            __syncthreads();
        }
    }

    if (tid < C) g_idx[b * C + tid] = si[tid];
}

// ---------------------------------------------------------------------------
// Kernel 3: fused bilinear-upsample + gated blend.
// Block = 16 output rows x 256 cols (256 threads, 16 px/thread, dense
// float4 lanes). ALL global loads (stage + 4 x-row loads) are front-batched
// before the single barrier -> per-thread MLP ~5. Stores interleaved per row.
// ---------------------------------------------------------------------------
__global__ void __launch_bounds__(256) fuse_kernel(
    const float* __restrict__ x,
    const float* __restrict__ readout,
    const float* __restrict__ weight,
    const float* __restrict__ bias,
    float* __restrict__ out)
{
    __shared__ float srow[10 * WR];

    const int plane = blockIdx.z;
    const int b = plane >> 6;
    const int c = plane & (C - 1);
    const int ch = g_idx[plane];

    const float* __restrict__ rsrc =
        readout + ((size_t)b * CR + ch) * (HR * WR);

    const int y0 = blockIdx.y << 4;          // 16 rows per block
    const float cst = (float)(127.0 / 255.0);

    int iy_lo = (int)((float)y0 * cst);        if (iy_lo > HR - 2) iy_lo = HR - 2;
    int iy_hi = (int)((float)(y0 + 15) * cst); if (iy_hi > HR - 2) iy_hi = HR - 2;
    iy_hi += 1;
    const int nrows = iy_hi - iy_lo + 1;      // <= 10

    const int tid = threadIdx.x;

    // ---- front-batched stage loads (up to 320 slots over 256 threads) ----
    const int nslots = nrows * 32;
    float4 sv0, sv1;
    const bool st0 = (tid < nslots);
    const bool st1 = (tid + 256 < nslots);
    if (st0)
        sv0 = __ldg((const float4*)(rsrc + (iy_lo + (tid >> 5)) * WR + ((tid & 31) << 2)));
    if (st1)
        sv1 = __ldg((const float4*)(rsrc + (iy_lo + ((tid + 256) >> 5)) * WR + (((tid + 256) & 31) << 2)));

    // ---- front-batched x loads: 4 rows, dense float4 lanes ----
    const int tx = tid & 63;                  // 64 threads cover 256 cols
    const int ty = tid >> 6;                  // 0..3
    const int x0 = tx << 2;

    size_t o[4];
    float4 xv[4];
    #pragma unroll
    for (int r = 0; r < 4; r++) {
        int y = y0 + ty + (r << 2);
        o[r] = ((size_t)plane * Hc + y) * Wc + x0;
        xv[r] = __ldcs((const float4*)(x + o[r]));
    }

    if (st0) *(float4*)(srow + (tid >> 5) * WR + ((tid & 31) << 2)) = sv0;
    if (st1) *(float4*)(srow + ((tid + 256) >> 5) * WR + (((tid + 256) & 31) << 2)) = sv1;
    __syncthreads();

    const float w0 = __ldg(weight + 2 * c);
    const float w1 = __ldg(weight + 2 * c + 1);
    const float bs = __ldg(bias + c);

    int   ixA[4];
    float wxA[4];
    #pragma unroll
    for (int k = 0; k < 4; k++) {
        float posx = (float)(x0 + k) * cst;
        int ix0 = (int)posx;
        if (ix0 > WR - 2) ix0 = WR - 2;
        ixA[k] = ix0;
        wxA[k] = posx - (float)ix0;
    }

    #pragma unroll
    for (int r = 0; r < 4; r++) {
        const int y = y0 + ty + (r << 2);
        float posy = (float)y * cst;
        int iy0 = (int)posy;
        if (iy0 > HR - 2) iy0 = HR - 2;
        const float wy = posy - (float)iy0;
        const float wy0 = 1.0f - wy;

        const float* __restrict__ s0 = srow + (iy0 - iy_lo) * WR;
        const float* __restrict__ s1 = s0 + WR;

        float xs[4] = {xv[r].x, xv[r].y, xv[r].z, xv[r].w};
        float os[4];
        #pragma unroll
        for (int k = 0; k < 4; k++) {
            int ix0 = ixA[k];
            // match reference: interpolate along H first, then W
            float a  = s0[ix0]     * wy0 + s1[ix0]     * wy;
            float bb = s0[ix0 + 1] * wy0 + s1[ix0 + 1] * wy;
            float rv = a * (1.0f - wxA[k]) + bb * wxA[k];
            float t = xs[k] * w0 + rv * w1 + bs;
            float gate = 1.0f / (1.0f + __expf(-t));
            os[k] = xs[k] + gate * (rv - xs[k]);
        }
        __stcs((float4*)(out + o[r]), make_float4(os[0], os[1], os[2], os[3]));
    }
}

// ---------------------------------------------------------------------------
extern "C" void kernel_launch(void* const* d_in, const int* in_sizes, int n_in,
                              void* d_out, int out_size)
{
    const float* x       = (const float*)d_in[0];
    const float* readout = (const float*)d_in[1];
    const float* weight  = (const float*)d_in[2];
    const float* bias    = (const float*)d_in[3];
    float* out = (float*)d_out;

    scores_kernel<<<B * CR, 256>>>(readout);
    topk_kernel<<<B, CR>>>();

    dim3 blk(256, 1, 1);
    dim3 grd(1, Hc / 16, B * C);   // (1, 16, 512) = 8192 blocks
    fuse_kernel<<<grd, blk>>>(x, readout, weight, bias, out);
}